// round 9
// baseline (speedup 1.0000x reference)
#include <cuda_runtime.h>
#include <math.h>

#define IMG 256
#define MAX_R 64
#define N_AG 2047
#define N_OB 2048
#define N_ENT 4095
#define FOVH 0.7853981633974483f   /* pi/4 = FOV/2 */
#define PT 1024
#define NB (IMG / 2)               /* 128 blocks, 2 columns each: single wave */

__global__ __launch_bounds__(PT)
void render_kernel(const float* __restrict__ agent,
                   const float* __restrict__ goal,
                   const float* __restrict__ others,
                   const float* __restrict__ obs,
                   float* __restrict__ out) {
    __shared__ uint2 s_rec0[N_ENT + 1];   /* col c0: {rem, depth_bits} */
    __shared__ uint2 s_rec1[N_ENT + 1];   /* col c1 */
    __shared__ int   s_wcnt[32];
    __shared__ int   s_wbase[33];         /* packed: cnt0<<16 | cnt1 */
    __shared__ float s_min[PT];

    int tid  = threadIdx.x;
    int warp = tid >> 5;
    unsigned lane = tid & 31;
    int c0 = blockIdx.x * 2;
    int c1 = c0 + 1;

    /* camera basis */
    float ax = agent[0], ay = agent[1];
    float vx = goal[0] - ax, vy = goal[1] - ay;
    float inv = 1.0f / (sqrtf(vx * vx + vy * vy) + 1e-8f);
    vx *= inv; vy *= inv;
    float c = vy, s = vx;

    /* Phase T/A: transform 4 entities per thread, hit-test both columns,
       double ballot compaction. */
    int rem0[4], rem1[4]; unsigned m0[4], m1[4], dep[4];
    int cnt0 = 0, cnt1 = 0;

    #pragma unroll
    for (int k = 0; k < 4; k++) {
        int e = tid + k * PT;
        float ex, ey, r, h;
        if (e < N_AG) {
            ex = others[2 * e];
            ey = others[2 * e + 1];
            r  = 0.05f;
            h  = 0.2f;
        } else if (e < N_ENT) {
            int o = e - N_AG;
            ex = obs[3 * o];
            ey = obs[3 * o + 1];
            r  = obs[3 * o + 2];
            h  = 0.5f;
        } else {
            ex = 1e9f; ey = -1e9f; r = 0.0f; h = 0.0f;   /* invalid */
        }

        float rx = ex - ax, ry = ey - ay;
        float camx =  c * rx + s * ry;
        float camy = -s * rx + c * ry;
        float dist = sqrtf(camx * camx + camy * camy);
        float angle = atan2f(camx, camy);

        rem0[k] = -1; rem1[k] = -1; dep[k] = 0u;
        if ((camy >= 0.0f) && (dist <= 3.0f) && (fabsf(angle) <= FOVH)) {
            float pixel_x = angle / FOVH * 0.5f;
            int pxi = (int)floorf((pixel_x + 0.5f) * (float)IMG);
            int pr  = (int)floorf(r / (dist + 1e-8f) * (float)IMG * 0.5f);
            pr = min(max(pr, 1), MAX_R);
            float depth = fminf(dist / 3.0f, 1.0f) * (1.0f - h * 0.3f);
            depth = fmaxf(depth, 0.0f);
            int pr2 = pr * pr;
            int dx0 = c0 - pxi;
            int dx1 = c1 - pxi;
            rem0[k] = pr2 - dx0 * dx0;
            rem1[k] = pr2 - dx1 * dx1;
            dep[k]  = __float_as_uint(depth);
        }
        m0[k] = __ballot_sync(0xffffffffu, rem0[k] >= 0);
        m1[k] = __ballot_sync(0xffffffffu, rem1[k] >= 0);
        cnt0 += __popc(m0[k]);
        cnt1 += __popc(m1[k]);
    }
    if (lane == 0) s_wcnt[warp] = (cnt0 << 16) | cnt1;
    __syncthreads();

    /* exclusive scan of packed warp counts (fields can't carry: sums < 2^16) */
    if (warp == 0) {
        int v = s_wcnt[lane];
        int incl = v;
        #pragma unroll
        for (int off = 1; off < 32; off <<= 1) {
            int t = __shfl_up_sync(0xffffffffu, incl, off);
            if ((int)lane >= off) incl += t;
        }
        s_wbase[lane] = incl - v;
        if (lane == 31) s_wbase[32] = incl;
    }
    __syncthreads();

    int base0 = s_wbase[warp] >> 16;
    int base1 = s_wbase[warp] & 0xffff;
    #pragma unroll
    for (int k = 0; k < 4; k++) {
        unsigned pre = (1u << lane) - 1u;
        if (rem0[k] >= 0)
            s_rec0[base0 + __popc(m0[k] & pre)] = make_uint2((unsigned)rem0[k], dep[k]);
        if (rem1[k] >= 0)
            s_rec1[base1 + __popc(m1[k] & pre)] = make_uint2((unsigned)rem1[k], dep[k]);
        base0 += __popc(m0[k]);
        base1 += __popc(m1[k]);
    }
    __syncthreads();
    int nc0 = s_wbase[32] >> 16;
    int nc1 = s_wbase[32] & 0xffff;

    /* Phase B: (row, colsel, half) per thread; rows with dy^2 > MAX_R^2 skip */
    int row    = tid & 255;
    int colsel = (tid >> 8) & 1;
    int half   = tid >> 9;
    int dy = row - IMG / 2;
    int d2 = dy * dy;
    const uint2* lst = colsel ? s_rec1 : s_rec0;
    int nc = colsel ? nc1 : nc0;

    float mv = 1.0f;
    if (d2 <= MAX_R * MAX_R) {
        #pragma unroll 4
        for (int e = half; e < nc; e += 2) {
            uint2 rr = lst[e];
            if (d2 <= (int)rr.x) mv = fminf(mv, __uint_as_float(rr.y));
        }
    }
    s_min[tid] = mv;
    __syncthreads();

    if (tid < 512) {
        int r2 = tid & 255;
        int cs = (tid >> 8) & 1;
        out[r2 * IMG + c0 + cs] = fminf(s_min[tid], s_min[tid + 512]);
    }
}

extern "C" void kernel_launch(void* const* d_in, const int* in_sizes, int n_in,
                              void* d_out, int out_size) {
    const float* agent  = (const float*)d_in[0];
    const float* goal   = (const float*)d_in[1];
    const float* others = (const float*)d_in[2];
    const float* obs    = (const float*)d_in[3];
    float* out          = (float*)d_out;

    render_kernel<<<NB, PT>>>(agent, goal, others, obs, out);
}